// round 15
// baseline (speedup 1.0000x reference)
#include <cuda_runtime.h>
#include <cuda_bf16.h>
#include <cstdint>
#include <cstddef>

#define Nn 100000
#define Ee 500000
#define Ll 5

// -------- scratch (device globals: allocation-free) --------
__device__ __align__(16) float g_h[(size_t)Nn * 128];
__device__ __align__(16) float g_agg[(size_t)Nn * 128];
__device__ __align__(16) float g_t1[(size_t)Nn * 256];
__device__ __align__(16) float g_t2[(size_t)Nn * 128];
__device__ __align__(16) __nv_bfloat16 g_wt1_hi[5 * 256 * 128];
__device__ __align__(16) __nv_bfloat16 g_wt1_lo[5 * 256 * 128];
__device__ __align__(16) __nv_bfloat16 g_wt2_hi[5 * 128 * 256];
__device__ __align__(16) __nv_bfloat16 g_wt2_lo[5 * 128 * 256];
__device__ float g_stats1[5 * 512];   // per-layer: 256 sums + 256 sumsq
__device__ float g_stats2[5 * 256];   // per-layer: 128 sums + 128 sumsq
// CSR scratch
__device__ int g_deg[Nn];
__device__ int g_rowptr[Nn + 1];
__device__ int g_cursor[Nn + 1];
__device__ int g_srcs[Ee];
__device__ int g_codes[Ee];
__device__ float g_ews[Ee];
__device__ int g_code[Ee];
__device__ int g_bsum[128];
__device__ __align__(16) float g_esum[5 * 512 * 128];

#define INV_N (1.0f / (float)Nn)

// ======================= PTX helpers =======================
__device__ __forceinline__ void mma_bf16(float* c, const uint32_t* a, uint32_t b0, uint32_t b1) {
    asm volatile(
        "mma.sync.aligned.m16n8k16.row.col.f32.bf16.bf16.f32 "
        "{%0,%1,%2,%3}, {%4,%5,%6,%7}, {%8,%9}, {%0,%1,%2,%3};"
        : "+f"(c[0]), "+f"(c[1]), "+f"(c[2]), "+f"(c[3])
        : "r"(a[0]), "r"(a[1]), "r"(a[2]), "r"(a[3]), "r"(b0), "r"(b1));
}
__device__ __forceinline__ void ldsm4(uint32_t addr, uint32_t* r) {
    asm volatile("ldmatrix.sync.aligned.m8n8.x4.shared.b16 {%0,%1,%2,%3}, [%4];"
                 : "=r"(r[0]), "=r"(r[1]), "=r"(r[2]), "=r"(r[3]) : "r"(addr));
}
#define CP_ASYNC16(dst, src) \
    asm volatile("cp.async.cg.shared.global [%0], [%1], 16;" :: "r"(dst), "l"(src))
#define CP_COMMIT() asm volatile("cp.async.commit_group;" ::: "memory")
#define CP_WAIT0()  asm volatile("cp.async.wait_group 0;" ::: "memory")

// ======================= fused setup =======================
// One launch: init h, zero deg/all-stats, transpose+split W1/W2, build esum.
__global__ void setup_kernel(const int* __restrict__ x, const float* __restrict__ ae,
                             const float* __restrict__ W1, const float* __restrict__ W2,
                             const float* __restrict__ be,
                             float* __restrict__ h,
                             __nv_bfloat16* __restrict__ wt1h, __nv_bfloat16* __restrict__ wt1l,
                             __nv_bfloat16* __restrict__ wt2h, __nv_bfloat16* __restrict__ wt2l,
                             float* __restrict__ esum,
                             int* __restrict__ deg,
                             float* __restrict__ st1, float* __restrict__ st2) {
    int idx = blockIdx.x * 256 + threadIdx.x;
    if (idx < Nn * 128) {
        int n = idx >> 7, d = idx & 127;
        float s = 0.f;
#pragma unroll
        for (int f = 0; f < 9; f++) {
            int xi = __ldg(x + n * 9 + f);
            s += __ldg(ae + (((size_t)(f * 120 + xi)) << 7) + d);
        }
        h[idx] = s;
    }
    if (idx < Nn) deg[idx] = 0;
    if (idx < 5 * 512) st1[idx] = 0.f;
    if (idx < 5 * 256) st2[idx] = 0.f;
    if (idx < 5 * 128 * 256) {   // W1: K=128, NC=256
        const int per = 128 * 256;
        int l = idx / per, r = idx - l * per;
        int n = r / 128, k = r - n * 128;
        float w = __ldg(W1 + (size_t)l * per + (size_t)k * 256 + n);
        __nv_bfloat16 hi = __float2bfloat16(w);
        wt1h[idx] = hi;
        wt1l[idx] = __float2bfloat16(w - __bfloat162float(hi));
        // W2: K=256, NC=128
        int n2 = r / 256, k2 = r - n2 * 256;
        float w2 = __ldg(W2 + (size_t)l * per + (size_t)k2 * 128 + n2);
        __nv_bfloat16 hi2 = __float2bfloat16(w2);
        wt2h[idx] = hi2;
        wt2l[idx] = __float2bfloat16(w2 - __bfloat162float(hi2));
    }
    if (idx < 5 * 512 * 128) {
        int l = idx / (512 * 128), r = idx - l * (512 * 128);
        int c = r >> 7, d = r & 127;
        int a0 = c >> 6, a1 = (c >> 3) & 7, a2 = c & 7;
        const float* b = be + (size_t)l * 3 * 8 * 128;
        esum[idx] = __ldg(b + a0 * 128 + d) + __ldg(b + (8 + a1) * 128 + d)
                  + __ldg(b + (16 + a2) * 128 + d);
    }
}

// ======================= CSR build =======================
__global__ void hist_kernel(const int* __restrict__ ei, const int* __restrict__ ea,
                            int* __restrict__ deg, int* __restrict__ code) {
    int e = blockIdx.x * 256 + threadIdx.x;
    if (e >= Ee) return;
    atomicAdd(&deg[__ldg(ei + Ee + e)], 1);
    int a0 = __ldg(ea + e * 3 + 0);
    int a1 = __ldg(ea + e * 3 + 1);
    int a2 = __ldg(ea + e * 3 + 2);
    code[e] = (a0 * 8 + a1) * 8 + a2;
}

// 3-phase parallel scan over deg (98 blocks of 1024)
__global__ void scanA_kernel(const int* __restrict__ deg, int* __restrict__ bsum) {
    __shared__ int wsum[32];
    int i = blockIdx.x * 1024 + threadIdx.x;
    int lane = threadIdx.x & 31, w = threadIdx.x >> 5;
    int v = (i < Nn) ? __ldg(deg + i) : 0;
#pragma unroll
    for (int o = 16; o; o >>= 1) v += __shfl_xor_sync(0xFFFFFFFFu, v, o);
    if (lane == 0) wsum[w] = v;
    __syncthreads();
    if (w == 0) {
        int s = wsum[lane];
#pragma unroll
        for (int o = 16; o; o >>= 1) s += __shfl_xor_sync(0xFFFFFFFFu, s, o);
        if (lane == 0) bsum[blockIdx.x] = s;
    }
}

__global__ void scanB_kernel(int* __restrict__ bsum, int nb) {
    // single warp: exclusive scan of nb (<=128) block sums
    __shared__ int tmp[128];
    int lane = threadIdx.x;          // 32 threads
    int carry = 0;
    for (int base = 0; base < nb; base += 32) {
        int i = base + lane;
        int v = (i < nb) ? bsum[i] : 0;
        int orig = v;
#pragma unroll
        for (int o = 1; o < 32; o <<= 1) {
            int t = __shfl_up_sync(0xFFFFFFFFu, v, o);
            if (lane >= o) v += t;
        }
        if (i < nb) tmp[i] = carry + v - orig;   // exclusive
        carry += __shfl_sync(0xFFFFFFFFu, v, 31);
    }
    __syncwarp();
    for (int i = lane; i < nb; i += 32) bsum[i] = tmp[i];
}

__global__ void scanC_kernel(const int* __restrict__ deg, const int* __restrict__ bsum,
                             int* __restrict__ rowptr, int* __restrict__ cursor) {
    __shared__ int wsum[32];
    int i = blockIdx.x * 1024 + threadIdx.x;
    int lane = threadIdx.x & 31, w = threadIdx.x >> 5;
    int v = (i < Nn) ? __ldg(deg + i) : 0;
#pragma unroll
    for (int o = 1; o < 32; o <<= 1) {
        int t = __shfl_up_sync(0xFFFFFFFFu, v, o);
        if (lane >= o) v += t;
    }
    if (lane == 31) wsum[w] = v;
    __syncthreads();
    if (w == 0) {
        int s = wsum[lane];
#pragma unroll
        for (int o = 1; o < 32; o <<= 1) {
            int t = __shfl_up_sync(0xFFFFFFFFu, s, o);
            if (lane >= o) s += t;
        }
        wsum[lane] = s;
    }
    __syncthreads();
    int incl = bsum[blockIdx.x] + (w > 0 ? wsum[w - 1] : 0) + v;
    if (i < Nn) { rowptr[i + 1] = incl; cursor[i + 1] = incl; }
    if (blockIdx.x == 0 && threadIdx.x == 0) { rowptr[0] = 0; cursor[0] = 0; }
}

__global__ void fill_kernel(const int* __restrict__ ei, const int* __restrict__ code,
                            const float* __restrict__ ew,
                            int* __restrict__ cursor,
                            int* __restrict__ srcs, int* __restrict__ codes,
                            float* __restrict__ ews) {
    int e = blockIdx.x * 256 + threadIdx.x;
    if (e >= Ee) return;
    int pos = atomicAdd(&cursor[__ldg(ei + Ee + e)], 1);
    srcs[pos]  = __ldg(ei + e);
    codes[pos] = __ldg(code + e);
    ews[pos]   = __ldg(ew + e);
}

// ======================= edge aggregation =======================
// warp-per-node gather. If stp != nullptr: h-value = relu(BN(src)) computed
// from stats slice stp + gamma/beta (finalize fused in).
__global__ void __launch_bounds__(256) edge_agg_kernel(
    const float* __restrict__ src_mat,
    const float* __restrict__ stp, const float* __restrict__ gp,
    const float* __restrict__ btp,
    const float* __restrict__ esum,
    const int* __restrict__ rowptr,
    const int* __restrict__ srcs, const int* __restrict__ codes,
    const float* __restrict__ ews, float* __restrict__ agg)
{
    __shared__ float ssc[128], ssh[128];
    const bool fuse = stp != nullptr;
    if (fuse && threadIdx.x < 128) {
        int c = threadIdx.x;
        float mu  = __ldg(stp + c) * INV_N;
        float var = __ldg(stp + 128 + c) * INV_N - mu * mu;
        float sc  = __ldg(gp + c) * rsqrtf(var + 1e-5f);
        ssc[c] = sc;
        ssh[c] = fmaf(-mu, sc, __ldg(btp + c));
    }
    __syncthreads();

    int node = (blockIdx.x * 256 + threadIdx.x) >> 5;
    int lane = threadIdx.x & 31;
    int d0 = lane * 4;
    float c0, c1, c2, c3, s0, s1, s2, s3;
    if (fuse) {
        c0 = ssc[d0]; c1 = ssc[d0 + 1]; c2 = ssc[d0 + 2]; c3 = ssc[d0 + 3];
        s0 = ssh[d0]; s1 = ssh[d0 + 1]; s2 = ssh[d0 + 2]; s3 = ssh[d0 + 3];
    }

    float a0 = 0.f, a1 = 0.f, a2 = 0.f, a3 = 0.f;
    int beg = __ldg(rowptr + node), end = __ldg(rowptr + node + 1);
    for (int i = beg; i < end; i++) {
        int src  = __ldg(srcs + i);
        int cd   = __ldg(codes + i);
        float w  = __ldg(ews + i);
        float4 hv = *(const float4*)(src_mat + (size_t)src * 128 + d0);
        if (fuse) {
            hv.x = fmaxf(fmaf(c0, hv.x, s0), 0.f);
            hv.y = fmaxf(fmaf(c1, hv.y, s1), 0.f);
            hv.z = fmaxf(fmaf(c2, hv.z, s2), 0.f);
            hv.w = fmaxf(fmaf(c3, hv.w, s3), 0.f);
        }
        const float4 ev = *(const float4*)(esum + (size_t)cd * 128 + d0);
        a0 = fmaf(fmaxf(hv.x + ev.x, 0.f), w, a0);
        a1 = fmaf(fmaxf(hv.y + ev.y, 0.f), w, a1);
        a2 = fmaf(fmaxf(hv.z + ev.z, 0.f), w, a2);
        a3 = fmaf(fmaxf(hv.w + ev.w, 0.f), w, a3);
    }
    *(float4*)(agg + (size_t)node * 128 + d0) = make_float4(a0, a1, a2, a3);
}

// final output: out = BN(t2), coefficients computed per block from stats
__global__ void apply_bn(const float* __restrict__ t2,
                         const float* __restrict__ stp, const float* __restrict__ gp,
                         const float* __restrict__ btp,
                         float* __restrict__ outp) {
    __shared__ float ssc[128], ssh[128];
    if (threadIdx.x < 128) {
        int c = threadIdx.x;
        float mu  = __ldg(stp + c) * INV_N;
        float var = __ldg(stp + 128 + c) * INV_N - mu * mu;
        float sc  = __ldg(gp + c) * rsqrtf(var + 1e-5f);
        ssc[c] = sc;
        ssh[c] = fmaf(-mu, sc, __ldg(btp + c));
    }
    __syncthreads();
    int idx = blockIdx.x * blockDim.x + threadIdx.x;
    if (idx >= Nn * 128) return;
    int c = idx & 127;
    outp[idx] = fmaf(ssc[c], t2[idx], ssh[c]);
}

// ======================= pipelined bf16 hi/lo mma GEMM =======================
// MODE 0: X = (1+eps)*A + A2
// MODE 1: X = relu(BN1(A))                      (BN from stats_prev, fused)
// MODE 2: X = (1+eps)*relu(BN2(A)) + A2         (BN from stats_prev, fused)
template <int K, int NC, int MODE>
__global__ void __launch_bounds__(256, 2) mma_gemm(
    const float* __restrict__ A, const float* __restrict__ A2,
    const float* __restrict__ epsp, int layer,
    const float* __restrict__ stats_prev, const float* __restrict__ g_prev,
    const float* __restrict__ bt_prev,
    const __nv_bfloat16* __restrict__ Wt_hi, const __nv_bfloat16* __restrict__ Wt_lo,
    const float* __restrict__ bias,
    float* __restrict__ C, float* __restrict__ stats)
{
    constexpr int CHUNKS = K / 32;
    constexpr int STG = 40960;
    constexpr int AH = 0, AL = 10240, BH = 20480, BL = 30720;
    constexpr int CC = (MODE == 1) ? 256 : 128;   // prev-BN channel count

    extern __shared__ char dsm[];
    __shared__ float s_sum[128];
    __shared__ float s_sq[128];
    __shared__ float sscsh[512];    // [0:CC) scale, [CC:2CC) shift

    uint32_t sb;
    asm("{ .reg .u64 t; cvta.to.shared.u64 t, %1; cvt.u32.u64 %0, t; }" : "=r"(sb) : "l"(dsm));

    const int tid  = threadIdx.x;
    const int wid  = tid >> 5, lane = tid & 31;
    const int g    = lane >> 2, t4 = lane & 3;
    const int wm   = wid & 3;
    const int wn   = wid >> 2;
    const int rowBase = blockIdx.x * 128;
    const int colBase = blockIdx.y * 128;

    if (tid < 128) { s_sum[tid] = 0.f; s_sq[tid] = 0.f; }

    // fused finalize-BN of the previous stage (each CTA computes redundantly)
    if (MODE != 0) {
        if (tid < CC) {
            float mu  = __ldg(stats_prev + tid) * INV_N;
            float var = __ldg(stats_prev + CC + tid) * INV_N - mu * mu;
            float sc  = __ldg(g_prev + tid) * rsqrtf(var + 1e-5f);
            sscsh[tid]      = sc;
            sscsh[CC + tid] = fmaf(-mu, sc, __ldg(bt_prev + tid));
        }
        __syncthreads();
    }

    float alpha = 1.0f;
    if (MODE != 1) alpha = 1.0f + __ldg(epsp + layer);

    const int lr  = tid >> 1;
    const int lk  = (tid & 1) * 16;
    const int lkb = (tid & 1) * 32;

    const int aoff = (wm * 32 + ((lane >> 3) & 1) * 8 + (lane & 7)) * 80 + (lane >> 4) * 16;
    const int boff = (wn * 64 + (lane >> 4) * 8 + (lane & 7)) * 80 + ((lane >> 3) & 1) * 16;

    float acc[2][8][4];
#pragma unroll
    for (int mt = 0; mt < 2; mt++)
#pragma unroll
        for (int nt = 0; nt < 8; nt++)
#pragma unroll
            for (int j = 0; j < 4; j++) acc[mt][nt][j] = 0.f;

    const int rg = rowBase + lr;
    const bool rv = rg < Nn;

    float4 pre[4];
    auto loadA = [&](int c) {
        const float* Ap = A + (size_t)rg * K + c * 32 + lk;
#pragma unroll
        for (int q = 0; q < 4; q++) {
            float4 v = make_float4(0.f, 0.f, 0.f, 0.f);
            if (rv) {
                float4 av = *(const float4*)(Ap + q * 4);
                int kg = c * 32 + lk + q * 4;
                if (MODE == 0) {
                    const float4 gv = *(const float4*)(A2 + (size_t)rg * K + kg);
                    v.x = fmaf(alpha, av.x, gv.x);
                    v.y = fmaf(alpha, av.y, gv.y);
                    v.z = fmaf(alpha, av.z, gv.z);
                    v.w = fmaf(alpha, av.w, gv.w);
                } else if (MODE == 1) {
                    v.x = fmaxf(fmaf(sscsh[kg + 0], av.x, sscsh[CC + kg + 0]), 0.f);
                    v.y = fmaxf(fmaf(sscsh[kg + 1], av.y, sscsh[CC + kg + 1]), 0.f);
                    v.z = fmaxf(fmaf(sscsh[kg + 2], av.z, sscsh[CC + kg + 2]), 0.f);
                    v.w = fmaxf(fmaf(sscsh[kg + 3], av.w, sscsh[CC + kg + 3]), 0.f);
                } else {
                    const float4 gv = *(const float4*)(A2 + (size_t)rg * K + kg);
                    float t0 = fmaxf(fmaf(sscsh[kg + 0], av.x, sscsh[CC + kg + 0]), 0.f);
                    float t1 = fmaxf(fmaf(sscsh[kg + 1], av.y, sscsh[CC + kg + 1]), 0.f);
                    float t2v = fmaxf(fmaf(sscsh[kg + 2], av.z, sscsh[CC + kg + 2]), 0.f);
                    float t3 = fmaxf(fmaf(sscsh[kg + 3], av.w, sscsh[CC + kg + 3]), 0.f);
                    v.x = fmaf(alpha, t0, gv.x);
                    v.y = fmaf(alpha, t1, gv.y);
                    v.z = fmaf(alpha, t2v, gv.z);
                    v.w = fmaf(alpha, t3, gv.w);
                }
            }
            pre[q] = v;
        }
    };
    auto cpasyncB = [&](int c, int stage) {
        const int n = colBase + lr;
        const __nv_bfloat16* Wh = Wt_hi + (size_t)n * K + c * 32 + lk;
        const __nv_bfloat16* Wl = Wt_lo + (size_t)n * K + c * 32 + lk;
        uint32_t dh = sb + stage * STG + BH + lr * 80 + lkb;
        uint32_t dl = sb + stage * STG + BL + lr * 80 + lkb;
        CP_ASYNC16(dh, Wh);
        CP_ASYNC16(dh + 16, Wh + 8);
        CP_ASYNC16(dl, Wl);
        CP_ASYNC16(dl + 16, Wl + 8);
    };
    auto storeA = [&](int stage) {
        uint32_t hi_d[8], lo_d[8];
#pragma unroll
        for (int q = 0; q < 4; q++) {
            float4 v = pre[q];
            __nv_bfloat162 h0 = __floats2bfloat162_rn(v.x, v.y);
            __nv_bfloat162 h1 = __floats2bfloat162_rn(v.z, v.w);
            float rx = v.x - __bfloat162float(h0.x);
            float ry = v.y - __bfloat162float(h0.y);
            float rz = v.z - __bfloat162float(h1.x);
            float rw = v.w - __bfloat162float(h1.y);
            __nv_bfloat162 l0 = __floats2bfloat162_rn(rx, ry);
            __nv_bfloat162 l1 = __floats2bfloat162_rn(rz, rw);
            hi_d[q * 2 + 0] = *(uint32_t*)&h0;
            hi_d[q * 2 + 1] = *(uint32_t*)&h1;
            lo_d[q * 2 + 0] = *(uint32_t*)&l0;
            lo_d[q * 2 + 1] = *(uint32_t*)&l1;
        }
        char* ah = dsm + stage * STG + AH + lr * 80 + lkb;
        char* al = dsm + stage * STG + AL + lr * 80 + lkb;
        *(uint4*)(ah)      = make_uint4(hi_d[0], hi_d[1], hi_d[2], hi_d[3]);
        *(uint4*)(ah + 16) = make_uint4(hi_d[4], hi_d[5], hi_d[6], hi_d[7]);
        *(uint4*)(al)      = make_uint4(lo_d[0], lo_d[1], lo_d[2], lo_d[3]);
        *(uint4*)(al + 16) = make_uint4(lo_d[4], lo_d[5], lo_d[6], lo_d[7]);
    };

    loadA(0);
    cpasyncB(0, 0);
    CP_COMMIT();
    storeA(0);
    CP_WAIT0();
    __syncthreads();

    for (int c = 0; c < CHUNKS; c++) {
        const int cur = c & 1, nxt = (c + 1) & 1;
        const bool more = (c + 1) < CHUNKS;
        if (more) {
            loadA(c + 1);
            cpasyncB(c + 1, nxt);
            CP_COMMIT();
        }

        const uint32_t base = sb + cur * STG;
#pragma unroll
        for (int ks = 0; ks < 2; ks++) {
            const int kb = ks * 32;
            uint32_t ah[2][4], al2[2][4];
#pragma unroll
            for (int mt = 0; mt < 2; mt++) {
                ldsm4(base + AH + aoff + mt * 1280 + kb, ah[mt]);
                ldsm4(base + AL + aoff + mt * 1280 + kb, al2[mt]);
            }
#pragma unroll
            for (int pp = 0; pp < 2; pp++) {
                uint32_t bh[2][4], bl[2][4];
                ldsm4(base + BH + boff + (2 * pp    ) * 1280 + kb, bh[0]);
                ldsm4(base + BH + boff + (2 * pp + 1) * 1280 + kb, bh[1]);
                ldsm4(base + BL + boff + (2 * pp    ) * 1280 + kb, bl[0]);
                ldsm4(base + BL + boff + (2 * pp + 1) * 1280 + kb, bl[1]);
#pragma unroll
                for (int q = 0; q < 2; q++) {
                    int p = 2 * pp + q;
#pragma unroll
                    for (int mt = 0; mt < 2; mt++) {
                        mma_bf16(acc[mt][2 * p],     al2[mt], bh[q][0], bh[q][1]);
                        mma_bf16(acc[mt][2 * p + 1], al2[mt], bh[q][2], bh[q][3]);
                    }
                }
#pragma unroll
                for (int q = 0; q < 2; q++) {
                    int p = 2 * pp + q;
#pragma unroll
                    for (int mt = 0; mt < 2; mt++) {
                        mma_bf16(acc[mt][2 * p],     ah[mt], bl[q][0], bl[q][1]);
                        mma_bf16(acc[mt][2 * p + 1], ah[mt], bl[q][2], bl[q][3]);
                    }
                }
#pragma unroll
                for (int q = 0; q < 2; q++) {
                    int p = 2 * pp + q;
#pragma unroll
                    for (int mt = 0; mt < 2; mt++) {
                        mma_bf16(acc[mt][2 * p],     ah[mt], bh[q][0], bh[q][1]);
                        mma_bf16(acc[mt][2 * p + 1], ah[mt], bh[q][2], bh[q][3]);
                    }
                }
            }
        }

        if (more) storeA(nxt);
        CP_WAIT0();
        __syncthreads();
    }

    // ---- epilogue ----
#pragma unroll
    for (int nt = 0; nt < 8; nt++) {
        int cl = wn * 64 + nt * 8 + t4 * 2;
        float b0 = __ldg(bias + colBase + cl);
        float b1 = __ldg(bias + colBase + cl + 1);
        float cs0 = 0.f, cq0 = 0.f, cs1 = 0.f, cq1 = 0.f;
#pragma unroll
        for (int mt = 0; mt < 2; mt++) {
            int r0 = rowBase + wm * 32 + mt * 16 + g;
#pragma unroll
            for (int half = 0; half < 2; half++) {
                int rr = r0 + half * 8;
                float v0 = acc[mt][nt][half * 2] + b0;
                float v1 = acc[mt][nt][half * 2 + 1] + b1;
                if (rr < Nn) {
                    *(float2*)(C + (size_t)rr * NC + colBase + cl) = make_float2(v0, v1);
                    cs0 += v0; cq0 += v0 * v0;
                    cs1 += v1; cq1 += v1 * v1;
                }
            }
        }
#pragma unroll
        for (int o = 4; o <= 16; o <<= 1) {
            cs0 += __shfl_xor_sync(0xFFFFFFFFu, cs0, o);
            cq0 += __shfl_xor_sync(0xFFFFFFFFu, cq0, o);
            cs1 += __shfl_xor_sync(0xFFFFFFFFu, cs1, o);
            cq1 += __shfl_xor_sync(0xFFFFFFFFu, cq1, o);
        }
        if (g == 0) {
            atomicAdd(&s_sum[cl], cs0);
            atomicAdd(&s_sq[cl], cq0);
            atomicAdd(&s_sum[cl + 1], cs1);
            atomicAdd(&s_sq[cl + 1], cq1);
        }
    }
    __syncthreads();
    if (tid < 128) {
        atomicAdd(&stats[colBase + tid],      s_sum[tid]);
        atomicAdd(&stats[NC + colBase + tid], s_sq[tid]);
    }
}

// ======================= launch =======================
extern "C" void kernel_launch(void* const* d_in, const int* in_sizes, int n_in,
                              void* d_out, int out_size) {
    const int*   x    = (const int*)d_in[0];
    const int*   ei   = (const int*)d_in[1];
    const int*   ea   = (const int*)d_in[2];
    const float* ew   = (const float*)d_in[3];
    const float* ae   = (const float*)d_in[4];
    const float* be   = (const float*)d_in[5];
    const float* eps  = (const float*)d_in[6];
    const float* W1   = (const float*)d_in[7];
    const float* b1   = (const float*)d_in[8];
    const float* g1   = (const float*)d_in[9];
    const float* bt1  = (const float*)d_in[10];
    const float* W2   = (const float*)d_in[11];
    const float* b2   = (const float*)d_in[12];
    const float* go   = (const float*)d_in[13];
    const float* bto  = (const float*)d_in[14];
    float* out = (float*)d_out;

    float *h, *agg, *t1, *t2, *st1, *st2, *esum, *ews;
    __nv_bfloat16 *wt1h, *wt1l, *wt2h, *wt2l;
    int *deg, *rowptr, *cursor, *srcs, *codes, *code, *bsum;
    cudaGetSymbolAddress((void**)&h,      g_h);
    cudaGetSymbolAddress((void**)&agg,    g_agg);
    cudaGetSymbolAddress((void**)&t1,     g_t1);
    cudaGetSymbolAddress((void**)&t2,     g_t2);
    cudaGetSymbolAddress((void**)&wt1h,   g_wt1_hi);
    cudaGetSymbolAddress((void**)&wt1l,   g_wt1_lo);
    cudaGetSymbolAddress((void**)&wt2h,   g_wt2_hi);
    cudaGetSymbolAddress((void**)&wt2l,   g_wt2_lo);
    cudaGetSymbolAddress((void**)&st1,    g_stats1);
    cudaGetSymbolAddress((void**)&st2,    g_stats2);
    cudaGetSymbolAddress((void**)&deg,    g_deg);
    cudaGetSymbolAddress((void**)&rowptr, g_rowptr);
    cudaGetSymbolAddress((void**)&cursor, g_cursor);
    cudaGetSymbolAddress((void**)&srcs,   g_srcs);
    cudaGetSymbolAddress((void**)&codes,  g_codes);
    cudaGetSymbolAddress((void**)&ews,    g_ews);
    cudaGetSymbolAddress((void**)&code,   g_code);
    cudaGetSymbolAddress((void**)&bsum,   g_bsum);
    cudaGetSymbolAddress((void**)&esum,   g_esum);

    const int DSMEM = 2 * 40960;
    cudaFuncSetAttribute(mma_gemm<128, 256, 0>,
                         cudaFuncAttributeMaxDynamicSharedMemorySize, DSMEM);
    cudaFuncSetAttribute(mma_gemm<128, 256, 2>,
                         cudaFuncAttributeMaxDynamicSharedMemorySize, DSMEM);
    cudaFuncSetAttribute(mma_gemm<256, 128, 1>,
                         cudaFuncAttributeMaxDynamicSharedMemorySize, DSMEM);

    const int elem_blocks = (Nn * 128 + 255) / 256;
    const int gemm_blocks = (Nn + 127) / 128;
    const int edge_blocks = (Ee + 255) / 256;
    const int scan_blocks = (Nn + 1023) / 1024;     // 98

    setup_kernel<<<elem_blocks, 256>>>(x, ae, W1, W2, be, h,
                                       wt1h, wt1l, wt2h, wt2l, esum, deg, st1, st2);
    hist_kernel<<<edge_blocks, 256>>>(ei, ea, deg, code);
    scanA_kernel<<<scan_blocks, 1024>>>(deg, bsum);
    scanB_kernel<<<1, 32>>>(bsum, scan_blocks);
    scanC_kernel<<<scan_blocks, 1024>>>(deg, bsum, rowptr, cursor);
    fill_kernel<<<edge_blocks, 256>>>(ei, code, ew, cursor, srcs, codes, ews);

    for (int l = 0; l < Ll; l++) {
        const size_t wo = (size_t)l * 128 * 256;
        const float* es = esum + (size_t)l * 512 * 128;
        float* s1 = st1 + l * 512;
        float* s2 = st2 + l * 256;
        const float* s2p = st2 + (l - 1) * 256;
        const float* gp  = go  + (l - 1) * 128;
        const float* btp = bto + (l - 1) * 128;

        dim3 grid1(gemm_blocks, 2);
        if (l == 0) {
            edge_agg_kernel<<<Nn / 8, 256>>>(h, (const float*)nullptr,
                                             (const float*)nullptr, (const float*)nullptr,
                                             es, rowptr, srcs, codes, ews, agg);
            mma_gemm<128, 256, 0><<<grid1, 256, DSMEM>>>(
                h, agg, eps, l,
                (const float*)nullptr, (const float*)nullptr, (const float*)nullptr,
                wt1h + wo, wt1l + wo, b1 + l * 256, t1, s1);
        } else {
            edge_agg_kernel<<<Nn / 8, 256>>>(t2, s2p, gp, btp,
                                             es, rowptr, srcs, codes, ews, agg);
            mma_gemm<128, 256, 2><<<grid1, 256, DSMEM>>>(
                t2, agg, eps, l, s2p, gp, btp,
                wt1h + wo, wt1l + wo, b1 + l * 256, t1, s1);
        }

        dim3 grid2(gemm_blocks, 1);
        mma_gemm<256, 128, 1><<<grid2, 256, DSMEM>>>(
            t1, (const float*)nullptr, (const float*)nullptr, 0,
            s1, g1 + l * 256, bt1 + l * 256,
            wt2h + wo, wt2l + wo, b2 + l * 128, t2, s2);
    }
    apply_bn<<<elem_blocks, 256>>>(t2, st2 + 4 * 256, go + 4 * 128, bto + 4 * 128, out);
}

// round 16
// speedup vs baseline: 1.3642x; 1.3642x over previous
#include <cuda_runtime.h>
#include <cuda_bf16.h>
#include <cstdint>
#include <cstddef>

#define Nn 100000
#define Ee 500000
#define Ll 5

// -------- scratch (device globals: allocation-free) --------
__device__ __align__(16) float g_h[(size_t)Nn * 128];
__device__ __align__(16) float g_agg[(size_t)Nn * 128];
__device__ __align__(16) float g_t1[(size_t)Nn * 256];
__device__ __align__(16) float g_t2[(size_t)Nn * 128];
__device__ __align__(16) __nv_bfloat16 g_wt1_hi[5 * 256 * 128];
__device__ __align__(16) __nv_bfloat16 g_wt1_lo[5 * 256 * 128];
__device__ __align__(16) __nv_bfloat16 g_wt2_hi[5 * 128 * 256];
__device__ __align__(16) __nv_bfloat16 g_wt2_lo[5 * 128 * 256];
__device__ float g_stats[768];
__device__ float g_sc1[512];
__device__ float g_sc2[256];
// CSR scratch
__device__ int g_deg[Nn];
__device__ int g_rowptr[Nn + 1];
__device__ int g_cursor[Nn + 1];
__device__ int g_srcs[Ee];
__device__ int g_codes[Ee];
__device__ float g_ews[Ee];
__device__ int g_code[Ee];
__device__ int g_bsum[128];
__device__ __align__(16) float g_esum[5 * 512 * 128];

// ======================= PTX helpers =======================
__device__ __forceinline__ void mma_bf16(float* c, const uint32_t* a, uint32_t b0, uint32_t b1) {
    asm volatile(
        "mma.sync.aligned.m16n8k16.row.col.f32.bf16.bf16.f32 "
        "{%0,%1,%2,%3}, {%4,%5,%6,%7}, {%8,%9}, {%0,%1,%2,%3};"
        : "+f"(c[0]), "+f"(c[1]), "+f"(c[2]), "+f"(c[3])
        : "r"(a[0]), "r"(a[1]), "r"(a[2]), "r"(a[3]), "r"(b0), "r"(b1));
}
__device__ __forceinline__ void ldsm4(uint32_t addr, uint32_t* r) {
    asm volatile("ldmatrix.sync.aligned.m8n8.x4.shared.b16 {%0,%1,%2,%3}, [%4];"
                 : "=r"(r[0]), "=r"(r[1]), "=r"(r[2]), "=r"(r[3]) : "r"(addr));
}
#define CP_ASYNC16(dst, src) \
    asm volatile("cp.async.cg.shared.global [%0], [%1], 16;" :: "r"(dst), "l"(src))
#define CP_COMMIT() asm volatile("cp.async.commit_group;" ::: "memory")
#define CP_WAIT0()  asm volatile("cp.async.wait_group 0;" ::: "memory")

// ======================= fused setup =======================
__global__ void setup_kernel(const int* __restrict__ x, const float* __restrict__ ae,
                             const float* __restrict__ W1, const float* __restrict__ W2,
                             const float* __restrict__ be,
                             float* __restrict__ h,
                             __nv_bfloat16* __restrict__ wt1h, __nv_bfloat16* __restrict__ wt1l,
                             __nv_bfloat16* __restrict__ wt2h, __nv_bfloat16* __restrict__ wt2l,
                             float* __restrict__ esum,
                             int* __restrict__ deg, float* __restrict__ stats) {
    int idx = blockIdx.x * 256 + threadIdx.x;
    if (idx < Nn * 128) {
        int n = idx >> 7, d = idx & 127;
        float s = 0.f;
#pragma unroll
        for (int f = 0; f < 9; f++) {
            int xi = __ldg(x + n * 9 + f);
            s += __ldg(ae + (((size_t)(f * 120 + xi)) << 7) + d);
        }
        h[idx] = s;
    }
    if (idx < Nn) deg[idx] = 0;
    if (idx < 768) stats[idx] = 0.f;
    if (idx < 5 * 128 * 256) {   // W1: K=128, NC=256
        const int per = 128 * 256;
        int l = idx / per, r = idx - l * per;
        int n = r / 128, k = r - n * 128;
        float w = __ldg(W1 + (size_t)l * per + (size_t)k * 256 + n);
        __nv_bfloat16 hi = __float2bfloat16(w);
        wt1h[idx] = hi;
        wt1l[idx] = __float2bfloat16(w - __bfloat162float(hi));
        // W2: K=256, NC=128
        int n2 = r / 256, k2 = r - n2 * 256;
        float w2 = __ldg(W2 + (size_t)l * per + (size_t)k2 * 128 + n2);
        __nv_bfloat16 hi2 = __float2bfloat16(w2);
        wt2h[idx] = hi2;
        wt2l[idx] = __float2bfloat16(w2 - __bfloat162float(hi2));
    }
    if (idx < 5 * 512 * 128) {
        int l = idx / (512 * 128), r = idx - l * (512 * 128);
        int c = r >> 7, d = r & 127;
        int a0 = c >> 6, a1 = (c >> 3) & 7, a2 = c & 7;
        const float* b = be + (size_t)l * 3 * 8 * 128;
        esum[idx] = __ldg(b + a0 * 128 + d) + __ldg(b + (8 + a1) * 128 + d)
                  + __ldg(b + (16 + a2) * 128 + d);
    }
}

// ======================= CSR build =======================
__global__ void hist_kernel(const int* __restrict__ ei, const int* __restrict__ ea,
                            int* __restrict__ deg, int* __restrict__ code) {
    int e = blockIdx.x * 256 + threadIdx.x;
    if (e >= Ee) return;
    atomicAdd(&deg[__ldg(ei + Ee + e)], 1);
    int a0 = __ldg(ea + e * 3 + 0);
    int a1 = __ldg(ea + e * 3 + 1);
    int a2 = __ldg(ea + e * 3 + 2);
    code[e] = (a0 * 8 + a1) * 8 + a2;
}

// 3-phase parallel scan over deg (98 blocks of 1024)
__global__ void scanA_kernel(const int* __restrict__ deg, int* __restrict__ bsum) {
    __shared__ int wsum[32];
    int i = blockIdx.x * 1024 + threadIdx.x;
    int lane = threadIdx.x & 31, w = threadIdx.x >> 5;
    int v = (i < Nn) ? __ldg(deg + i) : 0;
#pragma unroll
    for (int o = 16; o; o >>= 1) v += __shfl_xor_sync(0xFFFFFFFFu, v, o);
    if (lane == 0) wsum[w] = v;
    __syncthreads();
    if (w == 0) {
        int s = wsum[lane];
#pragma unroll
        for (int o = 16; o; o >>= 1) s += __shfl_xor_sync(0xFFFFFFFFu, s, o);
        if (lane == 0) bsum[blockIdx.x] = s;
    }
}

__global__ void scanB_kernel(int* __restrict__ bsum, int nb) {
    __shared__ int tmp[128];
    int lane = threadIdx.x;          // 32 threads
    int carry = 0;
    for (int base = 0; base < nb; base += 32) {
        int i = base + lane;
        int v = (i < nb) ? bsum[i] : 0;
        int orig = v;
#pragma unroll
        for (int o = 1; o < 32; o <<= 1) {
            int t = __shfl_up_sync(0xFFFFFFFFu, v, o);
            if (lane >= o) v += t;
        }
        if (i < nb) tmp[i] = carry + v - orig;   // exclusive
        carry += __shfl_sync(0xFFFFFFFFu, v, 31);
    }
    __syncwarp();
    for (int i = lane; i < nb; i += 32) bsum[i] = tmp[i];
}

__global__ void scanC_kernel(const int* __restrict__ deg, const int* __restrict__ bsum,
                             int* __restrict__ rowptr, int* __restrict__ cursor) {
    __shared__ int wsum[32];
    int i = blockIdx.x * 1024 + threadIdx.x;
    int lane = threadIdx.x & 31, w = threadIdx.x >> 5;
    int v = (i < Nn) ? __ldg(deg + i) : 0;
#pragma unroll
    for (int o = 1; o < 32; o <<= 1) {
        int t = __shfl_up_sync(0xFFFFFFFFu, v, o);
        if (lane >= o) v += t;
    }
    if (lane == 31) wsum[w] = v;
    __syncthreads();
    if (w == 0) {
        int s = wsum[lane];
#pragma unroll
        for (int o = 1; o < 32; o <<= 1) {
            int t = __shfl_up_sync(0xFFFFFFFFu, s, o);
            if (lane >= o) s += t;
        }
        wsum[lane] = s;
    }
    __syncthreads();
    int incl = bsum[blockIdx.x] + (w > 0 ? wsum[w - 1] : 0) + v;
    if (i < Nn) { rowptr[i + 1] = incl; cursor[i + 1] = incl; }
    if (blockIdx.x == 0 && threadIdx.x == 0) { rowptr[0] = 0; cursor[0] = 0; }
}

__global__ void fill_kernel(const int* __restrict__ ei, const int* __restrict__ code,
                            const float* __restrict__ ew,
                            int* __restrict__ cursor,
                            int* __restrict__ srcs, int* __restrict__ codes,
                            float* __restrict__ ews) {
    int e = blockIdx.x * 256 + threadIdx.x;
    if (e >= Ee) return;
    int pos = atomicAdd(&cursor[__ldg(ei + Ee + e)], 1);
    srcs[pos]  = __ldg(ei + e);
    codes[pos] = __ldg(code + e);
    ews[pos]   = __ldg(ew + e);
}

// ======================= small kernels =======================
__global__ void __launch_bounds__(256) edge_agg_kernel(
    const float* __restrict__ src_mat, const float* __restrict__ sc,
    const float* __restrict__ esum,
    const int* __restrict__ rowptr,
    const int* __restrict__ srcs, const int* __restrict__ codes,
    const float* __restrict__ ews, float* __restrict__ agg)
{
    __shared__ float ssc[128], ssh[128];
    if (sc && threadIdx.x < 128) {
        ssc[threadIdx.x] = sc[threadIdx.x];
        ssh[threadIdx.x] = sc[128 + threadIdx.x];
    }
    __syncthreads();

    int node = (blockIdx.x * 256 + threadIdx.x) >> 5;
    int lane = threadIdx.x & 31;
    int d0 = lane * 4;
    const bool fuse = sc != nullptr;
    float c0, c1, c2, c3, s0, s1, s2, s3;
    if (fuse) {
        c0 = ssc[d0]; c1 = ssc[d0 + 1]; c2 = ssc[d0 + 2]; c3 = ssc[d0 + 3];
        s0 = ssh[d0]; s1 = ssh[d0 + 1]; s2 = ssh[d0 + 2]; s3 = ssh[d0 + 3];
    }

    float a0 = 0.f, a1 = 0.f, a2 = 0.f, a3 = 0.f;
    int beg = __ldg(rowptr + node), end = __ldg(rowptr + node + 1);
    for (int i = beg; i < end; i++) {
        int src  = __ldg(srcs + i);
        int cd   = __ldg(codes + i);
        float w  = __ldg(ews + i);
        float4 hv = *(const float4*)(src_mat + (size_t)src * 128 + d0);
        if (fuse) {
            hv.x = fmaxf(fmaf(c0, hv.x, s0), 0.f);
            hv.y = fmaxf(fmaf(c1, hv.y, s1), 0.f);
            hv.z = fmaxf(fmaf(c2, hv.z, s2), 0.f);
            hv.w = fmaxf(fmaf(c3, hv.w, s3), 0.f);
        }
        const float4 ev = *(const float4*)(esum + (size_t)cd * 128 + d0);
        a0 = fmaf(fmaxf(hv.x + ev.x, 0.f), w, a0);
        a1 = fmaf(fmaxf(hv.y + ev.y, 0.f), w, a1);
        a2 = fmaf(fmaxf(hv.z + ev.z, 0.f), w, a2);
        a3 = fmaf(fmaxf(hv.w + ev.w, 0.f), w, a3);
    }
    *(float4*)(agg + (size_t)node * 128 + d0) = make_float4(a0, a1, a2, a3);
}

__global__ void finalize_bn(float* __restrict__ stats,
                            const float* __restrict__ g,
                            const float* __restrict__ bt,
                            float* __restrict__ scsh, int Cc) {
    int c = blockIdx.x * blockDim.x + threadIdx.x;
    if (c >= Cc) return;
    const float inv = 1.0f / (float)Nn;
    float mu  = stats[c] * inv;
    float var = stats[Cc + c] * inv - mu * mu;
    float sc  = __ldg(g + c) * rsqrtf(var + 1e-5f);
    scsh[c]      = sc;
    scsh[Cc + c] = fmaf(-mu, sc, __ldg(bt + c));
    stats[c] = 0.f;
    stats[Cc + c] = 0.f;
}

__global__ void apply_bn(const float* __restrict__ t2,
                         const float* __restrict__ scsh,
                         float* __restrict__ outp) {
    int idx = blockIdx.x * blockDim.x + threadIdx.x;
    if (idx >= Nn * 128) return;
    int c = idx & 127;
    outp[idx] = fmaf(scsh[c], t2[idx], scsh[128 + c]);
}

// ======================= pipelined bf16 hi/lo mma GEMM (R14-proven) =======================
// MODE 0: X = (1+eps)*A + A2
// MODE 1: X = relu(sc[k]*A + sh[k])
// MODE 2: X = (1+eps)*relu(sc[k]*A + sh[k]) + A2
template <int K, int NC, int MODE>
__global__ void __launch_bounds__(256, 2) mma_gemm(
    const float* __restrict__ A, const float* __restrict__ A2,
    const float* __restrict__ epsp, int layer,
    const float* __restrict__ scsh,
    const __nv_bfloat16* __restrict__ Wt_hi, const __nv_bfloat16* __restrict__ Wt_lo,
    const float* __restrict__ bias,
    float* __restrict__ C, float* __restrict__ stats)
{
    constexpr int CHUNKS = K / 32;
    constexpr int STG = 40960;
    constexpr int AH = 0, AL = 10240, BH = 20480, BL = 30720;

    extern __shared__ char dsm[];
    __shared__ float s_sum[128];
    __shared__ float s_sq[128];

    uint32_t sb;
    asm("{ .reg .u64 t; cvta.to.shared.u64 t, %1; cvt.u32.u64 %0, t; }" : "=r"(sb) : "l"(dsm));

    const int tid  = threadIdx.x;
    const int wid  = tid >> 5, lane = tid & 31;
    const int g    = lane >> 2, t4 = lane & 3;
    const int wm   = wid & 3;
    const int wn   = wid >> 2;
    const int rowBase = blockIdx.x * 128;
    const int colBase = blockIdx.y * 128;

    if (tid < 128) { s_sum[tid] = 0.f; s_sq[tid] = 0.f; }

    float alpha = 1.0f;
    if (MODE != 1) alpha = 1.0f + __ldg(epsp + layer);
    const float* shv = scsh + K;

    const int lr  = tid >> 1;
    const int lk  = (tid & 1) * 16;
    const int lkb = (tid & 1) * 32;

    const int aoff = (wm * 32 + ((lane >> 3) & 1) * 8 + (lane & 7)) * 80 + (lane >> 4) * 16;
    const int boff = (wn * 64 + (lane >> 4) * 8 + (lane & 7)) * 80 + ((lane >> 3) & 1) * 16;

    float acc[2][8][4];
#pragma unroll
    for (int mt = 0; mt < 2; mt++)
#pragma unroll
        for (int nt = 0; nt < 8; nt++)
#pragma unroll
            for (int j = 0; j < 4; j++) acc[mt][nt][j] = 0.f;

    const int rg = rowBase + lr;
    const bool rv = rg < Nn;

    float4 pre[4];
    auto loadA = [&](int c) {
        const float* Ap = A + (size_t)rg * K + c * 32 + lk;
#pragma unroll
        for (int q = 0; q < 4; q++) {
            float4 v = make_float4(0.f, 0.f, 0.f, 0.f);
            if (rv) {
                float4 av = *(const float4*)(Ap + q * 4);
                int kg = c * 32 + lk + q * 4;
                if (MODE == 0) {
                    const float4 gv = *(const float4*)(A2 + (size_t)rg * K + kg);
                    v.x = fmaf(alpha, av.x, gv.x);
                    v.y = fmaf(alpha, av.y, gv.y);
                    v.z = fmaf(alpha, av.z, gv.z);
                    v.w = fmaf(alpha, av.w, gv.w);
                } else if (MODE == 1) {
                    v.x = fmaxf(fmaf(__ldg(scsh + kg + 0), av.x, __ldg(shv + kg + 0)), 0.f);
                    v.y = fmaxf(fmaf(__ldg(scsh + kg + 1), av.y, __ldg(shv + kg + 1)), 0.f);
                    v.z = fmaxf(fmaf(__ldg(scsh + kg + 2), av.z, __ldg(shv + kg + 2)), 0.f);
                    v.w = fmaxf(fmaf(__ldg(scsh + kg + 3), av.w, __ldg(shv + kg + 3)), 0.f);
                } else {
                    const float4 gv = *(const float4*)(A2 + (size_t)rg * K + kg);
                    float t0 = fmaxf(fmaf(__ldg(scsh + kg + 0), av.x, __ldg(shv + kg + 0)), 0.f);
                    float t1 = fmaxf(fmaf(__ldg(scsh + kg + 1), av.y, __ldg(shv + kg + 1)), 0.f);
                    float t2v = fmaxf(fmaf(__ldg(scsh + kg + 2), av.z, __ldg(shv + kg + 2)), 0.f);
                    float t3 = fmaxf(fmaf(__ldg(scsh + kg + 3), av.w, __ldg(shv + kg + 3)), 0.f);
                    v.x = fmaf(alpha, t0, gv.x);
                    v.y = fmaf(alpha, t1, gv.y);
                    v.z = fmaf(alpha, t2v, gv.z);
                    v.w = fmaf(alpha, t3, gv.w);
                }
            }
            pre[q] = v;
        }
    };
    auto cpasyncB = [&](int c, int stage) {
        const int n = colBase + lr;
        const __nv_bfloat16* Wh = Wt_hi + (size_t)n * K + c * 32 + lk;
        const __nv_bfloat16* Wl = Wt_lo + (size_t)n * K + c * 32 + lk;
        uint32_t dh = sb + stage * STG + BH + lr * 80 + lkb;
        uint32_t dl = sb + stage * STG + BL + lr * 80 + lkb;
        CP_ASYNC16(dh, Wh);
        CP_ASYNC16(dh + 16, Wh + 8);
        CP_ASYNC16(dl, Wl);
        CP_ASYNC16(dl + 16, Wl + 8);
    };
    auto storeA = [&](int stage) {
        uint32_t hi_d[8], lo_d[8];
#pragma unroll
        for (int q = 0; q < 4; q++) {
            float4 v = pre[q];
            __nv_bfloat162 h0 = __floats2bfloat162_rn(v.x, v.y);
            __nv_bfloat162 h1 = __floats2bfloat162_rn(v.z, v.w);
            float rx = v.x - __bfloat162float(h0.x);
            float ry = v.y - __bfloat162float(h0.y);
            float rz = v.z - __bfloat162float(h1.x);
            float rw = v.w - __bfloat162float(h1.y);
            __nv_bfloat162 l0 = __floats2bfloat162_rn(rx, ry);
            __nv_bfloat162 l1 = __floats2bfloat162_rn(rz, rw);
            hi_d[q * 2 + 0] = *(uint32_t*)&h0;
            hi_d[q * 2 + 1] = *(uint32_t*)&h1;
            lo_d[q * 2 + 0] = *(uint32_t*)&l0;
            lo_d[q * 2 + 1] = *(uint32_t*)&l1;
        }
        char* ah = dsm + stage * STG + AH + lr * 80 + lkb;
        char* al = dsm + stage * STG + AL + lr * 80 + lkb;
        *(uint4*)(ah)      = make_uint4(hi_d[0], hi_d[1], hi_d[2], hi_d[3]);
        *(uint4*)(ah + 16) = make_uint4(hi_d[4], hi_d[5], hi_d[6], hi_d[7]);
        *(uint4*)(al)      = make_uint4(lo_d[0], lo_d[1], lo_d[2], lo_d[3]);
        *(uint4*)(al + 16) = make_uint4(lo_d[4], lo_d[5], lo_d[6], lo_d[7]);
    };

    loadA(0);
    cpasyncB(0, 0);
    CP_COMMIT();
    storeA(0);
    CP_WAIT0();
    __syncthreads();

    for (int c = 0; c < CHUNKS; c++) {
        const int cur = c & 1, nxt = (c + 1) & 1;
        const bool more = (c + 1) < CHUNKS;
        if (more) {
            loadA(c + 1);
            cpasyncB(c + 1, nxt);
            CP_COMMIT();
        }

        const uint32_t base = sb + cur * STG;
#pragma unroll
        for (int ks = 0; ks < 2; ks++) {
            const int kb = ks * 32;
            uint32_t ah[2][4], al2[2][4];
#pragma unroll
            for (int mt = 0; mt < 2; mt++) {
                ldsm4(base + AH + aoff + mt * 1280 + kb, ah[mt]);
                ldsm4(base + AL + aoff + mt * 1280 + kb, al2[mt]);
            }
#pragma unroll
            for (int pp = 0; pp < 2; pp++) {
                uint32_t bh[2][4], bl[2][4];
                ldsm4(base + BH + boff + (2 * pp    ) * 1280 + kb, bh[0]);
                ldsm4(base + BH + boff + (2 * pp + 1) * 1280 + kb, bh[1]);
                ldsm4(base + BL + boff + (2 * pp    ) * 1280 + kb, bl[0]);
                ldsm4(base + BL + boff + (2 * pp + 1) * 1280 + kb, bl[1]);
#pragma unroll
                for (int q = 0; q < 2; q++) {
                    int p = 2 * pp + q;
#pragma unroll
                    for (int mt = 0; mt < 2; mt++) {
                        mma_bf16(acc[mt][2 * p],     al2[mt], bh[q][0], bh[q][1]);
                        mma_bf16(acc[mt][2 * p + 1], al2[mt], bh[q][2], bh[q][3]);
                    }
                }
#pragma unroll
                for (int q = 0; q < 2; q++) {
                    int p = 2 * pp + q;
#pragma unroll
                    for (int mt = 0; mt < 2; mt++) {
                        mma_bf16(acc[mt][2 * p],     ah[mt], bl[q][0], bl[q][1]);
                        mma_bf16(acc[mt][2 * p + 1], ah[mt], bl[q][2], bl[q][3]);
                    }
                }
#pragma unroll
                for (int q = 0; q < 2; q++) {
                    int p = 2 * pp + q;
#pragma unroll
                    for (int mt = 0; mt < 2; mt++) {
                        mma_bf16(acc[mt][2 * p],     ah[mt], bh[q][0], bh[q][1]);
                        mma_bf16(acc[mt][2 * p + 1], ah[mt], bh[q][2], bh[q][3]);
                    }
                }
            }
        }

        if (more) storeA(nxt);
        CP_WAIT0();
        __syncthreads();
    }

    // ---- epilogue ----
#pragma unroll
    for (int nt = 0; nt < 8; nt++) {
        int cl = wn * 64 + nt * 8 + t4 * 2;
        float b0 = __ldg(bias + colBase + cl);
        float b1 = __ldg(bias + colBase + cl + 1);
        float cs0 = 0.f, cq0 = 0.f, cs1 = 0.f, cq1 = 0.f;
#pragma unroll
        for (int mt = 0; mt < 2; mt++) {
            int r0 = rowBase + wm * 32 + mt * 16 + g;
#pragma unroll
            for (int half = 0; half < 2; half++) {
                int rr = r0 + half * 8;
                float v0 = acc[mt][nt][half * 2] + b0;
                float v1 = acc[mt][nt][half * 2 + 1] + b1;
                if (rr < Nn) {
                    *(float2*)(C + (size_t)rr * NC + colBase + cl) = make_float2(v0, v1);
                    cs0 += v0; cq0 += v0 * v0;
                    cs1 += v1; cq1 += v1 * v1;
                }
            }
        }
#pragma unroll
        for (int o = 4; o <= 16; o <<= 1) {
            cs0 += __shfl_xor_sync(0xFFFFFFFFu, cs0, o);
            cq0 += __shfl_xor_sync(0xFFFFFFFFu, cq0, o);
            cs1 += __shfl_xor_sync(0xFFFFFFFFu, cs1, o);
            cq1 += __shfl_xor_sync(0xFFFFFFFFu, cq1, o);
        }
        if (g == 0) {
            atomicAdd(&s_sum[cl], cs0);
            atomicAdd(&s_sq[cl], cq0);
            atomicAdd(&s_sum[cl + 1], cs1);
            atomicAdd(&s_sq[cl + 1], cq1);
        }
    }
    __syncthreads();
    if (tid < 128) {
        atomicAdd(&stats[colBase + tid],      s_sum[tid]);
        atomicAdd(&stats[NC + colBase + tid], s_sq[tid]);
    }
}

// ======================= launch =======================
extern "C" void kernel_launch(void* const* d_in, const int* in_sizes, int n_in,
                              void* d_out, int out_size) {
    const int*   x    = (const int*)d_in[0];
    const int*   ei   = (const int*)d_in[1];
    const int*   ea   = (const int*)d_in[2];
    const float* ew   = (const float*)d_in[3];
    const float* ae   = (const float*)d_in[4];
    const float* be   = (const float*)d_in[5];
    const float* eps  = (const float*)d_in[6];
    const float* W1   = (const float*)d_in[7];
    const float* b1   = (const float*)d_in[8];
    const float* g1   = (const float*)d_in[9];
    const float* bt1  = (const float*)d_in[10];
    const float* W2   = (const float*)d_in[11];
    const float* b2   = (const float*)d_in[12];
    const float* go   = (const float*)d_in[13];
    const float* bto  = (const float*)d_in[14];
    float* out = (float*)d_out;

    float *h, *agg, *t1, *t2, *stats, *sc1, *sc2, *esum, *ews;
    __nv_bfloat16 *wt1h, *wt1l, *wt2h, *wt2l;
    int *deg, *rowptr, *cursor, *srcs, *codes, *code, *bsum;
    cudaGetSymbolAddress((void**)&h,      g_h);
    cudaGetSymbolAddress((void**)&agg,    g_agg);
    cudaGetSymbolAddress((void**)&t1,     g_t1);
    cudaGetSymbolAddress((void**)&t2,     g_t2);
    cudaGetSymbolAddress((void**)&wt1h,   g_wt1_hi);
    cudaGetSymbolAddress((void**)&wt1l,   g_wt1_lo);
    cudaGetSymbolAddress((void**)&wt2h,   g_wt2_hi);
    cudaGetSymbolAddress((void**)&wt2l,   g_wt2_lo);
    cudaGetSymbolAddress((void**)&stats,  g_stats);
    cudaGetSymbolAddress((void**)&sc1,    g_sc1);
    cudaGetSymbolAddress((void**)&sc2,    g_sc2);
    cudaGetSymbolAddress((void**)&deg,    g_deg);
    cudaGetSymbolAddress((void**)&rowptr, g_rowptr);
    cudaGetSymbolAddress((void**)&cursor, g_cursor);
    cudaGetSymbolAddress((void**)&srcs,   g_srcs);
    cudaGetSymbolAddress((void**)&codes,  g_codes);
    cudaGetSymbolAddress((void**)&ews,    g_ews);
    cudaGetSymbolAddress((void**)&code,   g_code);
    cudaGetSymbolAddress((void**)&bsum,   g_bsum);
    cudaGetSymbolAddress((void**)&esum,   g_esum);
    float* st1 = stats;
    float* st2 = stats + 512;

    const int DSMEM = 2 * 40960;
    cudaFuncSetAttribute(mma_gemm<128, 256, 0>,
                         cudaFuncAttributeMaxDynamicSharedMemorySize, DSMEM);
    cudaFuncSetAttribute(mma_gemm<128, 256, 2>,
                         cudaFuncAttributeMaxDynamicSharedMemorySize, DSMEM);
    cudaFuncSetAttribute(mma_gemm<256, 128, 1>,
                         cudaFuncAttributeMaxDynamicSharedMemorySize, DSMEM);

    const int elem_blocks = (Nn * 128 + 255) / 256;
    const int gemm_blocks = (Nn + 127) / 128;
    const int edge_blocks = (Ee + 255) / 256;
    const int scan_blocks = (Nn + 1023) / 1024;     // 98

    setup_kernel<<<elem_blocks, 256>>>(x, ae, W1, W2, be, h,
                                       wt1h, wt1l, wt2h, wt2l, esum, deg, stats);
    hist_kernel<<<edge_blocks, 256>>>(ei, ea, deg, code);
    scanA_kernel<<<scan_blocks, 1024>>>(deg, bsum);
    scanB_kernel<<<1, 32>>>(bsum, scan_blocks);
    scanC_kernel<<<scan_blocks, 1024>>>(deg, bsum, rowptr, cursor);
    fill_kernel<<<edge_blocks, 256>>>(ei, code, ew, cursor, srcs, codes, ews);

    for (int l = 0; l < Ll; l++) {
        const size_t wo = (size_t)l * 128 * 256;
        const float* es = esum + (size_t)l * 512 * 128;

        dim3 grid1(gemm_blocks, 2);
        if (l == 0) {
            edge_agg_kernel<<<Nn / 8, 256>>>(h, (const float*)nullptr, es,
                                             rowptr, srcs, codes, ews, agg);
            mma_gemm<128, 256, 0><<<grid1, 256, DSMEM>>>(
                h, agg, eps, l, (const float*)nullptr,
                wt1h + wo, wt1l + wo, b1 + l * 256, t1, st1);
        } else {
            edge_agg_kernel<<<Nn / 8, 256>>>(t2, sc2, es,
                                             rowptr, srcs, codes, ews, agg);
            mma_gemm<128, 256, 2><<<grid1, 256, DSMEM>>>(
                t2, agg, eps, l, sc2,
                wt1h + wo, wt1l + wo, b1 + l * 256, t1, st1);
        }
        finalize_bn<<<1, 256>>>(st1, g1 + l * 256, bt1 + l * 256, sc1, 256);

        dim3 grid2(gemm_blocks, 1);
        mma_gemm<256, 128, 1><<<grid2, 256, DSMEM>>>(
            t1, (const float*)nullptr, (const float*)nullptr, 0, sc1,
            wt2h + wo, wt2l + wo, b2 + l * 128, t2, st2);
        finalize_bn<<<1, 128>>>(st2, go + l * 128, bto + l * 128, sc2, 128);
    }
    apply_bn<<<elem_blocks, 256>>>(t2, sc2, out);
}

// round 17
// speedup vs baseline: 1.3708x; 1.0048x over previous
#include <cuda_runtime.h>
#include <cuda_bf16.h>
#include <cstdint>
#include <cstddef>

#define Nn 100000
#define Ee 500000
#define Ll 5

// -------- scratch (device globals: allocation-free) --------
__device__ __align__(16) float g_h[(size_t)Nn * 128];
__device__ __align__(16) float g_agg[(size_t)Nn * 128];
__device__ __align__(16) float g_t1[(size_t)Nn * 256];
__device__ __align__(16) float g_t2[(size_t)Nn * 128];
__device__ __align__(16) __nv_bfloat16 g_wt1_hi[5 * 256 * 128];
__device__ __align__(16) __nv_bfloat16 g_wt1_lo[5 * 256 * 128];
__device__ __align__(16) __nv_bfloat16 g_wt2_hi[5 * 128 * 256];
__device__ __align__(16) __nv_bfloat16 g_wt2_lo[5 * 128 * 256];
__device__ float g_stats[768];
__device__ float g_sc1[512];
__device__ float g_sc2[256];
// CSR scratch
__device__ int g_deg[Nn];
__device__ int g_rowptr[Nn + 1];
__device__ int g_cursor[Nn + 1];
__device__ int g_srcs[Ee];
__device__ int g_codes[Ee];
__device__ float g_ews[Ee];
__device__ int g_code[Ee];
__device__ int g_bsum[128];
__device__ __align__(16) float g_esum[5 * 512 * 128];

// ======================= PTX helpers =======================
__device__ __forceinline__ void mma_bf16(float* c, const uint32_t* a, uint32_t b0, uint32_t b1) {
    asm volatile(
        "mma.sync.aligned.m16n8k16.row.col.f32.bf16.bf16.f32 "
        "{%0,%1,%2,%3}, {%4,%5,%6,%7}, {%8,%9}, {%0,%1,%2,%3};"
        : "+f"(c[0]), "+f"(c[1]), "+f"(c[2]), "+f"(c[3])
        : "r"(a[0]), "r"(a[1]), "r"(a[2]), "r"(a[3]), "r"(b0), "r"(b1));
}
__device__ __forceinline__ void ldsm4(uint32_t addr, uint32_t* r) {
    asm volatile("ldmatrix.sync.aligned.m8n8.x4.shared.b16 {%0,%1,%2,%3}, [%4];"
                 : "=r"(r[0]), "=r"(r[1]), "=r"(r[2]), "=r"(r[3]) : "r"(addr));
}
#define CP_ASYNC16(dst, src) \
    asm volatile("cp.async.cg.shared.global [%0], [%1], 16;" :: "r"(dst), "l"(src))
#define CP_COMMIT() asm volatile("cp.async.commit_group;" ::: "memory")
#define CP_WAIT0()  asm volatile("cp.async.wait_group 0;" ::: "memory")

// ======================= fused setup =======================
__global__ void setup_kernel(const int* __restrict__ x, const float* __restrict__ ae,
                             const float* __restrict__ W1, const float* __restrict__ W2,
                             const float* __restrict__ be,
                             float* __restrict__ h,
                             __nv_bfloat16* __restrict__ wt1h, __nv_bfloat16* __restrict__ wt1l,
                             __nv_bfloat16* __restrict__ wt2h, __nv_bfloat16* __restrict__ wt2l,
                             float* __restrict__ esum,
                             int* __restrict__ deg, float* __restrict__ stats) {
    int idx = blockIdx.x * 256 + threadIdx.x;
    if (idx < Nn * 128) {
        int n = idx >> 7, d = idx & 127;
        float s = 0.f;
#pragma unroll
        for (int f = 0; f < 9; f++) {
            int xi = __ldg(x + n * 9 + f);
            s += __ldg(ae + (((size_t)(f * 120 + xi)) << 7) + d);
        }
        h[idx] = s;
    }
    if (idx < Nn) deg[idx] = 0;
    if (idx < 768) stats[idx] = 0.f;
    if (idx < 5 * 128 * 256) {   // W1: K=128, NC=256
        const int per = 128 * 256;
        int l = idx / per, r = idx - l * per;
        int n = r / 128, k = r - n * 128;
        float w = __ldg(W1 + (size_t)l * per + (size_t)k * 256 + n);
        __nv_bfloat16 hi = __float2bfloat16(w);
        wt1h[idx] = hi;
        wt1l[idx] = __float2bfloat16(w - __bfloat162float(hi));
        // W2: K=256, NC=128
        int n2 = r / 256, k2 = r - n2 * 256;
        float w2 = __ldg(W2 + (size_t)l * per + (size_t)k2 * 128 + n2);
        __nv_bfloat16 hi2 = __float2bfloat16(w2);
        wt2h[idx] = hi2;
        wt2l[idx] = __float2bfloat16(w2 - __bfloat162float(hi2));
    }
    if (idx < 5 * 512 * 128) {
        int l = idx / (512 * 128), r = idx - l * (512 * 128);
        int c = r >> 7, d = r & 127;
        int a0 = c >> 6, a1 = (c >> 3) & 7, a2 = c & 7;
        const float* b = be + (size_t)l * 3 * 8 * 128;
        esum[idx] = __ldg(b + a0 * 128 + d) + __ldg(b + (8 + a1) * 128 + d)
                  + __ldg(b + (16 + a2) * 128 + d);
    }
}

// ======================= CSR build =======================
__global__ void hist_kernel(const int* __restrict__ ei, const int* __restrict__ ea,
                            int* __restrict__ deg, int* __restrict__ code) {
    int e = blockIdx.x * 256 + threadIdx.x;
    if (e >= Ee) return;
    atomicAdd(&deg[__ldg(ei + Ee + e)], 1);
    int a0 = __ldg(ea + e * 3 + 0);
    int a1 = __ldg(ea + e * 3 + 1);
    int a2 = __ldg(ea + e * 3 + 2);
    code[e] = (a0 * 8 + a1) * 8 + a2;
}

// 2-phase parallel scan over deg (98 blocks of 1024)
__global__ void scanA_kernel(const int* __restrict__ deg, int* __restrict__ bsum) {
    __shared__ int wsum[32];
    int i = blockIdx.x * 1024 + threadIdx.x;
    int lane = threadIdx.x & 31, w = threadIdx.x >> 5;
    int v = (i < Nn) ? __ldg(deg + i) : 0;
#pragma unroll
    for (int o = 16; o; o >>= 1) v += __shfl_xor_sync(0xFFFFFFFFu, v, o);
    if (lane == 0) wsum[w] = v;
    __syncthreads();
    if (w == 0) {
        int s = wsum[lane];
#pragma unroll
        for (int o = 16; o; o >>= 1) s += __shfl_xor_sync(0xFFFFFFFFu, s, o);
        if (lane == 0) bsum[blockIdx.x] = s;
    }
}

// scanC: each block computes its own exclusive offset over bsum (98 ints),
// then writes rowptr/cursor. scanB launch eliminated.
__global__ void scanC_kernel(const int* __restrict__ deg, const int* __restrict__ bsum,
                             int nb,
                             int* __restrict__ rowptr, int* __restrict__ cursor) {
    __shared__ int wsum[32];
    __shared__ int s_off;
    int lane = threadIdx.x & 31, w = threadIdx.x >> 5;

    // warp 0: exclusive prefix of bsum up to blockIdx.x
    if (w == 0) {
        int acc = 0;
        for (int base = 0; base < nb; base += 32) {
            int j = base + lane;
            int v = (j < nb && j < blockIdx.x) ? __ldg(bsum + j) : 0;
#pragma unroll
            for (int o = 16; o; o >>= 1) v += __shfl_xor_sync(0xFFFFFFFFu, v, o);
            acc += v;
        }
        if (lane == 0) s_off = acc;
    }

    int i = blockIdx.x * 1024 + threadIdx.x;
    int v = (i < Nn) ? __ldg(deg + i) : 0;
#pragma unroll
    for (int o = 1; o < 32; o <<= 1) {
        int t = __shfl_up_sync(0xFFFFFFFFu, v, o);
        if (lane >= o) v += t;
    }
    if (lane == 31) wsum[w] = v;
    __syncthreads();
    if (w == 0) {
        int s = wsum[lane];
#pragma unroll
        for (int o = 1; o < 32; o <<= 1) {
            int t = __shfl_up_sync(0xFFFFFFFFu, s, o);
            if (lane >= o) s += t;
        }
        wsum[lane] = s;
    }
    __syncthreads();
    int incl = s_off + (w > 0 ? wsum[w - 1] : 0) + v;
    if (i < Nn) { rowptr[i + 1] = incl; cursor[i + 1] = incl; }
    if (blockIdx.x == 0 && threadIdx.x == 0) { rowptr[0] = 0; cursor[0] = 0; }
}

__global__ void fill_kernel(const int* __restrict__ ei, const int* __restrict__ code,
                            const float* __restrict__ ew,
                            int* __restrict__ cursor,
                            int* __restrict__ srcs, int* __restrict__ codes,
                            float* __restrict__ ews) {
    int e = blockIdx.x * 256 + threadIdx.x;
    if (e >= Ee) return;
    int pos = atomicAdd(&cursor[__ldg(ei + Ee + e)], 1);
    srcs[pos]  = __ldg(ei + e);
    codes[pos] = __ldg(code + e);
    ews[pos]   = __ldg(ew + e);
}

// ======================= edge aggregation (x2 unrolled) =======================
__global__ void __launch_bounds__(256) edge_agg_kernel(
    const float* __restrict__ src_mat, const float* __restrict__ sc,
    const float* __restrict__ esum,
    const int* __restrict__ rowptr,
    const int* __restrict__ srcs, const int* __restrict__ codes,
    const float* __restrict__ ews, float* __restrict__ agg)
{
    __shared__ float ssc[128], ssh[128];
    if (sc && threadIdx.x < 128) {
        ssc[threadIdx.x] = sc[threadIdx.x];
        ssh[threadIdx.x] = sc[128 + threadIdx.x];
    }
    __syncthreads();

    int node = (blockIdx.x * 256 + threadIdx.x) >> 5;
    int lane = threadIdx.x & 31;
    int d0 = lane * 4;
    const bool fuse = sc != nullptr;
    float c0, c1, c2, c3, s0, s1, s2, s3;
    if (fuse) {
        c0 = ssc[d0]; c1 = ssc[d0 + 1]; c2 = ssc[d0 + 2]; c3 = ssc[d0 + 3];
        s0 = ssh[d0]; s1 = ssh[d0 + 1]; s2 = ssh[d0 + 2]; s3 = ssh[d0 + 3];
    }

    float a0 = 0.f, a1 = 0.f, a2 = 0.f, a3 = 0.f;
    const int beg = __ldg(rowptr + node), end = __ldg(rowptr + node + 1);
    int i = beg;
    for (; i + 2 <= end; i += 2) {
        int src0  = __ldg(srcs + i);
        int src1  = __ldg(srcs + i + 1);
        int cd0   = __ldg(codes + i);
        int cd1   = __ldg(codes + i + 1);
        float w0  = __ldg(ews + i);
        float w1  = __ldg(ews + i + 1);
        float4 hv0 = *(const float4*)(src_mat + (size_t)src0 * 128 + d0);
        float4 hv1 = *(const float4*)(src_mat + (size_t)src1 * 128 + d0);
        const float4 ev0 = *(const float4*)(esum + (size_t)cd0 * 128 + d0);
        const float4 ev1 = *(const float4*)(esum + (size_t)cd1 * 128 + d0);
        if (fuse) {
            hv0.x = fmaxf(fmaf(c0, hv0.x, s0), 0.f);
            hv0.y = fmaxf(fmaf(c1, hv0.y, s1), 0.f);
            hv0.z = fmaxf(fmaf(c2, hv0.z, s2), 0.f);
            hv0.w = fmaxf(fmaf(c3, hv0.w, s3), 0.f);
            hv1.x = fmaxf(fmaf(c0, hv1.x, s0), 0.f);
            hv1.y = fmaxf(fmaf(c1, hv1.y, s1), 0.f);
            hv1.z = fmaxf(fmaf(c2, hv1.z, s2), 0.f);
            hv1.w = fmaxf(fmaf(c3, hv1.w, s3), 0.f);
        }
        a0 = fmaf(fmaxf(hv0.x + ev0.x, 0.f), w0, a0);
        a1 = fmaf(fmaxf(hv0.y + ev0.y, 0.f), w0, a1);
        a2 = fmaf(fmaxf(hv0.z + ev0.z, 0.f), w0, a2);
        a3 = fmaf(fmaxf(hv0.w + ev0.w, 0.f), w0, a3);
        a0 = fmaf(fmaxf(hv1.x + ev1.x, 0.f), w1, a0);
        a1 = fmaf(fmaxf(hv1.y + ev1.y, 0.f), w1, a1);
        a2 = fmaf(fmaxf(hv1.z + ev1.z, 0.f), w1, a2);
        a3 = fmaf(fmaxf(hv1.w + ev1.w, 0.f), w1, a3);
    }
    if (i < end) {
        int src  = __ldg(srcs + i);
        int cd   = __ldg(codes + i);
        float w  = __ldg(ews + i);
        float4 hv = *(const float4*)(src_mat + (size_t)src * 128 + d0);
        if (fuse) {
            hv.x = fmaxf(fmaf(c0, hv.x, s0), 0.f);
            hv.y = fmaxf(fmaf(c1, hv.y, s1), 0.f);
            hv.z = fmaxf(fmaf(c2, hv.z, s2), 0.f);
            hv.w = fmaxf(fmaf(c3, hv.w, s3), 0.f);
        }
        const float4 ev = *(const float4*)(esum + (size_t)cd * 128 + d0);
        a0 = fmaf(fmaxf(hv.x + ev.x, 0.f), w, a0);
        a1 = fmaf(fmaxf(hv.y + ev.y, 0.f), w, a1);
        a2 = fmaf(fmaxf(hv.z + ev.z, 0.f), w, a2);
        a3 = fmaf(fmaxf(hv.w + ev.w, 0.f), w, a3);
    }
    *(float4*)(agg + (size_t)node * 128 + d0) = make_float4(a0, a1, a2, a3);
}

__global__ void finalize_bn(float* __restrict__ stats,
                            const float* __restrict__ g,
                            const float* __restrict__ bt,
                            float* __restrict__ scsh, int Cc) {
    int c = blockIdx.x * blockDim.x + threadIdx.x;
    if (c >= Cc) return;
    const float inv = 1.0f / (float)Nn;
    float mu  = stats[c] * inv;
    float var = stats[Cc + c] * inv - mu * mu;
    float sc  = __ldg(g + c) * rsqrtf(var + 1e-5f);
    scsh[c]      = sc;
    scsh[Cc + c] = fmaf(-mu, sc, __ldg(bt + c));
    stats[c] = 0.f;
    stats[Cc + c] = 0.f;
}

__global__ void apply_bn(const float* __restrict__ t2,
                         const float* __restrict__ scsh,
                         float* __restrict__ outp) {
    int idx = blockIdx.x * blockDim.x + threadIdx.x;
    if (idx >= Nn * 128) return;
    int c = idx & 127;
    outp[idx] = fmaf(scsh[c], t2[idx], scsh[128 + c]);
}

// ======================= pipelined bf16 hi/lo mma GEMM (frozen, R14/R16-proven) ===========
// MODE 0: X = (1+eps)*A + A2
// MODE 1: X = relu(sc[k]*A + sh[k])
// MODE 2: X = (1+eps)*relu(sc[k]*A + sh[k]) + A2
template <int K, int NC, int MODE>
__global__ void __launch_bounds__(256, 2) mma_gemm(
    const float* __restrict__ A, const float* __restrict__ A2,
    const float* __restrict__ epsp, int layer,
    const float* __restrict__ scsh,
    const __nv_bfloat16* __restrict__ Wt_hi, const __nv_bfloat16* __restrict__ Wt_lo,
    const float* __restrict__ bias,
    float* __restrict__ C, float* __restrict__ stats)
{
    constexpr int CHUNKS = K / 32;
    constexpr int STG = 40960;
    constexpr int AH = 0, AL = 10240, BH = 20480, BL = 30720;

    extern __shared__ char dsm[];
    __shared__ float s_sum[128];
    __shared__ float s_sq[128];

    uint32_t sb;
    asm("{ .reg .u64 t; cvta.to.shared.u64 t, %1; cvt.u32.u64 %0, t; }" : "=r"(sb) : "l"(dsm));

    const int tid  = threadIdx.x;
    const int wid  = tid >> 5, lane = tid & 31;
    const int g    = lane >> 2, t4 = lane & 3;
    const int wm   = wid & 3;
    const int wn   = wid >> 2;
    const int rowBase = blockIdx.x * 128;
    const int colBase = blockIdx.y * 128;

    if (tid < 128) { s_sum[tid] = 0.f; s_sq[tid] = 0.f; }

    float alpha = 1.0f;
    if (MODE != 1) alpha = 1.0f + __ldg(epsp + layer);
    const float* shv = scsh + K;

    const int lr  = tid >> 1;
    const int lk  = (tid & 1) * 16;
    const int lkb = (tid & 1) * 32;

    const int aoff = (wm * 32 + ((lane >> 3) & 1) * 8 + (lane & 7)) * 80 + (lane >> 4) * 16;
    const int boff = (wn * 64 + (lane >> 4) * 8 + (lane & 7)) * 80 + ((lane >> 3) & 1) * 16;

    float acc[2][8][4];
#pragma unroll
    for (int mt = 0; mt < 2; mt++)
#pragma unroll
        for (int nt = 0; nt < 8; nt++)
#pragma unroll
            for (int j = 0; j < 4; j++) acc[mt][nt][j] = 0.f;

    const int rg = rowBase + lr;
    const bool rv = rg < Nn;

    float4 pre[4];
    auto loadA = [&](int c) {
        const float* Ap = A + (size_t)rg * K + c * 32 + lk;
#pragma unroll
        for (int q = 0; q < 4; q++) {
            float4 v = make_float4(0.f, 0.f, 0.f, 0.f);
            if (rv) {
                float4 av = *(const float4*)(Ap + q * 4);
                int kg = c * 32 + lk + q * 4;
                if (MODE == 0) {
                    const float4 gv = *(const float4*)(A2 + (size_t)rg * K + kg);
                    v.x = fmaf(alpha, av.x, gv.x);
                    v.y = fmaf(alpha, av.y, gv.y);
                    v.z = fmaf(alpha, av.z, gv.z);
                    v.w = fmaf(alpha, av.w, gv.w);
                } else if (MODE == 1) {
                    v.x = fmaxf(fmaf(__ldg(scsh + kg + 0), av.x, __ldg(shv + kg + 0)), 0.f);
                    v.y = fmaxf(fmaf(__ldg(scsh + kg + 1), av.y, __ldg(shv + kg + 1)), 0.f);
                    v.z = fmaxf(fmaf(__ldg(scsh + kg + 2), av.z, __ldg(shv + kg + 2)), 0.f);
                    v.w = fmaxf(fmaf(__ldg(scsh + kg + 3), av.w, __ldg(shv + kg + 3)), 0.f);
                } else {
                    const float4 gv = *(const float4*)(A2 + (size_t)rg * K + kg);
                    float t0 = fmaxf(fmaf(__ldg(scsh + kg + 0), av.x, __ldg(shv + kg + 0)), 0.f);
                    float t1 = fmaxf(fmaf(__ldg(scsh + kg + 1), av.y, __ldg(shv + kg + 1)), 0.f);
                    float t2v = fmaxf(fmaf(__ldg(scsh + kg + 2), av.z, __ldg(shv + kg + 2)), 0.f);
                    float t3 = fmaxf(fmaf(__ldg(scsh + kg + 3), av.w, __ldg(shv + kg + 3)), 0.f);
                    v.x = fmaf(alpha, t0, gv.x);
                    v.y = fmaf(alpha, t1, gv.y);
                    v.z = fmaf(alpha, t2v, gv.z);
                    v.w = fmaf(alpha, t3, gv.w);
                }
            }
            pre[q] = v;
        }
    };
    auto cpasyncB = [&](int c, int stage) {
        const int n = colBase + lr;
        const __nv_bfloat16* Wh = Wt_hi + (size_t)n * K + c * 32 + lk;
        const __nv_bfloat16* Wl = Wt_lo + (size_t)n * K + c * 32 + lk;
        uint32_t dh = sb + stage * STG + BH + lr * 80 + lkb;
        uint32_t dl = sb + stage * STG + BL + lr * 80 + lkb;
        CP_ASYNC16(dh, Wh);
        CP_ASYNC16(dh + 16, Wh + 8);
        CP_ASYNC16(dl, Wl);
        CP_ASYNC16(dl + 16, Wl + 8);
    };
    auto storeA = [&](int stage) {
        uint32_t hi_d[8], lo_d[8];
#pragma unroll
        for (int q = 0; q < 4; q++) {
            float4 v = pre[q];
            __nv_bfloat162 h0 = __floats2bfloat162_rn(v.x, v.y);
            __nv_bfloat162 h1 = __floats2bfloat162_rn(v.z, v.w);
            float rx = v.x - __bfloat162float(h0.x);
            float ry = v.y - __bfloat162float(h0.y);
            float rz = v.z - __bfloat162float(h1.x);
            float rw = v.w - __bfloat162float(h1.y);
            __nv_bfloat162 l0 = __floats2bfloat162_rn(rx, ry);
            __nv_bfloat162 l1 = __floats2bfloat162_rn(rz, rw);
            hi_d[q * 2 + 0] = *(uint32_t*)&h0;
            hi_d[q * 2 + 1] = *(uint32_t*)&h1;
            lo_d[q * 2 + 0] = *(uint32_t*)&l0;
            lo_d[q * 2 + 1] = *(uint32_t*)&l1;
        }
        char* ah = dsm + stage * STG + AH + lr * 80 + lkb;
        char* al = dsm + stage * STG + AL + lr * 80 + lkb;
        *(uint4*)(ah)      = make_uint4(hi_d[0], hi_d[1], hi_d[2], hi_d[3]);
        *(uint4*)(ah + 16) = make_uint4(hi_d[4], hi_d[5], hi_d[6], hi_d[7]);
        *(uint4*)(al)      = make_uint4(lo_d[0], lo_d[1], lo_d[2], lo_d[3]);
        *(uint4*)(al + 16) = make_uint4(lo_d[4], lo_d[5], lo_d[6], lo_d[7]);
    };

    loadA(0);
    cpasyncB(0, 0);
    CP_COMMIT();
    storeA(0);
    CP_WAIT0();
    __syncthreads();

    for (int c = 0; c < CHUNKS; c++) {
        const int cur = c & 1, nxt = (c + 1) & 1;
        const bool more = (c + 1) < CHUNKS;
        if (more) {
            loadA(c + 1);
            cpasyncB(c + 1, nxt);
            CP_COMMIT();
        }

        const uint32_t base = sb + cur * STG;
#pragma unroll
        for (int ks = 0; ks < 2; ks++) {
            const int kb = ks * 32;
            uint32_t ah[2][4], al2[2][4];
#pragma unroll
            for (int mt = 0; mt < 2; mt++) {
                ldsm4(base + AH + aoff + mt * 1280 + kb, ah[mt]);
                ldsm4(base + AL + aoff + mt * 1280 + kb, al2[mt]);
            }
#pragma unroll
            for (int pp = 0; pp < 2; pp++) {
                uint32_t bh[2][4], bl[2][4];
                ldsm4(base + BH + boff + (2 * pp    ) * 1280 + kb, bh[0]);
                ldsm4(base + BH + boff + (2 * pp + 1) * 1280 + kb, bh[1]);
                ldsm4(base + BL + boff + (2 * pp    ) * 1280 + kb, bl[0]);
                ldsm4(base + BL + boff + (2 * pp + 1) * 1280 + kb, bl[1]);
#pragma unroll
                for (int q = 0; q < 2; q++) {
                    int p = 2 * pp + q;
#pragma unroll
                    for (int mt = 0; mt < 2; mt++) {
                        mma_bf16(acc[mt][2 * p],     al2[mt], bh[q][0], bh[q][1]);
                        mma_bf16(acc[mt][2 * p + 1], al2[mt], bh[q][2], bh[q][3]);
                    }
                }
#pragma unroll
                for (int q = 0; q < 2; q++) {
                    int p = 2 * pp + q;
#pragma unroll
                    for (int mt = 0; mt < 2; mt++) {
                        mma_bf16(acc[mt][2 * p],     ah[mt], bl[q][0], bl[q][1]);
                        mma_bf16(acc[mt][2 * p + 1], ah[mt], bl[q][2], bl[q][3]);
                    }
                }
#pragma unroll
                for (int q = 0; q < 2; q++) {
                    int p = 2 * pp + q;
#pragma unroll
                    for (int mt = 0; mt < 2; mt++) {
                        mma_bf16(acc[mt][2 * p],     ah[mt], bh[q][0], bh[q][1]);
                        mma_bf16(acc[mt][2 * p + 1], ah[mt], bh[q][2], bh[q][3]);
                    }
                }
            }
        }

        if (more) storeA(nxt);
        CP_WAIT0();
        __syncthreads();
    }

    // ---- epilogue ----
#pragma unroll
    for (int nt = 0; nt < 8; nt++) {
        int cl = wn * 64 + nt * 8 + t4 * 2;
        float b0 = __ldg(bias + colBase + cl);
        float b1 = __ldg(bias + colBase + cl + 1);
        float cs0 = 0.f, cq0 = 0.f, cs1 = 0.f, cq1 = 0.f;
#pragma unroll
        for (int mt = 0; mt < 2; mt++) {
            int r0 = rowBase + wm * 32 + mt * 16 + g;
#pragma unroll
            for (int half = 0; half < 2; half++) {
                int rr = r0 + half * 8;
                float v0 = acc[mt][nt][half * 2] + b0;
                float v1 = acc[mt][nt][half * 2 + 1] + b1;
                if (rr < Nn) {
                    *(float2*)(C + (size_t)rr * NC + colBase + cl) = make_float2(v0, v1);
                    cs0 += v0; cq0 += v0 * v0;
                    cs1 += v1; cq1 += v1 * v1;
                }
            }
        }
#pragma unroll
        for (int o = 4; o <= 16; o <<= 1) {
            cs0 += __shfl_xor_sync(0xFFFFFFFFu, cs0, o);
            cq0 += __shfl_xor_sync(0xFFFFFFFFu, cq0, o);
            cs1 += __shfl_xor_sync(0xFFFFFFFFu, cs1, o);
            cq1 += __shfl_xor_sync(0xFFFFFFFFu, cq1, o);
        }
        if (g == 0) {
            atomicAdd(&s_sum[cl], cs0);
            atomicAdd(&s_sq[cl], cq0);
            atomicAdd(&s_sum[cl + 1], cs1);
            atomicAdd(&s_sq[cl + 1], cq1);
        }
    }
    __syncthreads();
    if (tid < 128) {
        atomicAdd(&stats[colBase + tid],      s_sum[tid]);
        atomicAdd(&stats[NC + colBase + tid], s_sq[tid]);
    }
}

// ======================= launch =======================
extern "C" void kernel_launch(void* const* d_in, const int* in_sizes, int n_in,
                              void* d_out, int out_size) {
    const int*   x    = (const int*)d_in[0];
    const int*   ei   = (const int*)d_in[1];
    const int*   ea   = (const int*)d_in[2];
    const float* ew   = (const float*)d_in[3];
    const float* ae   = (const float*)d_in[4];
    const float* be   = (const float*)d_in[5];
    const float* eps  = (const float*)d_in[6];
    const float* W1   = (const float*)d_in[7];
    const float* b1   = (const float*)d_in[8];
    const float* g1   = (const float*)d_in[9];
    const float* bt1  = (const float*)d_in[10];
    const float* W2   = (const float*)d_in[11];
    const float* b2   = (const float*)d_in[12];
    const float* go   = (const float*)d_in[13];
    const float* bto  = (const float*)d_in[14];
    float* out = (float*)d_out;

    float *h, *agg, *t1, *t2, *stats, *sc1, *sc2, *esum, *ews;
    __nv_bfloat16 *wt1h, *wt1l, *wt2h, *wt2l;
    int *deg, *rowptr, *cursor, *srcs, *codes, *code, *bsum;
    cudaGetSymbolAddress((void**)&h,      g_h);
    cudaGetSymbolAddress((void**)&agg,    g_agg);
    cudaGetSymbolAddress((void**)&t1,     g_t1);
    cudaGetSymbolAddress((void**)&t2,     g_t2);
    cudaGetSymbolAddress((void**)&wt1h,   g_wt1_hi);
    cudaGetSymbolAddress((void**)&wt1l,   g_wt1_lo);
    cudaGetSymbolAddress((void**)&wt2h,   g_wt2_hi);
    cudaGetSymbolAddress((void**)&wt2l,   g_wt2_lo);
    cudaGetSymbolAddress((void**)&stats,  g_stats);
    cudaGetSymbolAddress((void**)&sc1,    g_sc1);
    cudaGetSymbolAddress((void**)&sc2,    g_sc2);
    cudaGetSymbolAddress((void**)&deg,    g_deg);
    cudaGetSymbolAddress((void**)&rowptr, g_rowptr);
    cudaGetSymbolAddress((void**)&cursor, g_cursor);
    cudaGetSymbolAddress((void**)&srcs,   g_srcs);
    cudaGetSymbolAddress((void**)&codes,  g_codes);
    cudaGetSymbolAddress((void**)&ews,    g_ews);
    cudaGetSymbolAddress((void**)&code,   g_code);
    cudaGetSymbolAddress((void**)&bsum,   g_bsum);
    cudaGetSymbolAddress((void**)&esum,   g_esum);
    float* st1 = stats;
    float* st2 = stats + 512;

    const int DSMEM = 2 * 40960;
    cudaFuncSetAttribute(mma_gemm<128, 256, 0>,
                         cudaFuncAttributeMaxDynamicSharedMemorySize, DSMEM);
    cudaFuncSetAttribute(mma_gemm<128, 256, 2>,
                         cudaFuncAttributeMaxDynamicSharedMemorySize, DSMEM);
    cudaFuncSetAttribute(mma_gemm<256, 128, 1>,
                         cudaFuncAttributeMaxDynamicSharedMemorySize, DSMEM);

    const int elem_blocks = (Nn * 128 + 255) / 256;
    const int gemm_blocks = (Nn + 127) / 128;
    const int edge_blocks = (Ee + 255) / 256;
    const int scan_blocks = (Nn + 1023) / 1024;     // 98

    setup_kernel<<<elem_blocks, 256>>>(x, ae, W1, W2, be, h,
                                       wt1h, wt1l, wt2h, wt2l, esum, deg, stats);
    hist_kernel<<<edge_blocks, 256>>>(ei, ea, deg, code);
    scanA_kernel<<<scan_blocks, 1024>>>(deg, bsum);
    scanC_kernel<<<scan_blocks, 1024>>>(deg, bsum, scan_blocks, rowptr, cursor);
    fill_kernel<<<edge_blocks, 256>>>(ei, code, ew, cursor, srcs, codes, ews);

    for (int l = 0; l < Ll; l++) {
        const size_t wo = (size_t)l * 128 * 256;
        const float* es = esum + (size_t)l * 512 * 128;

        dim3 grid1(gemm_blocks, 2);
        if (l == 0) {
            edge_agg_kernel<<<Nn / 8, 256>>>(h, (const float*)nullptr, es,
                                             rowptr, srcs, codes, ews, agg);
            mma_gemm<128, 256, 0><<<grid1, 256, DSMEM>>>(
                h, agg, eps, l, (const float*)nullptr,
                wt1h + wo, wt1l + wo, b1 + l * 256, t1, st1);
        } else {
            edge_agg_kernel<<<Nn / 8, 256>>>(t2, sc2, es,
                                             rowptr, srcs, codes, ews, agg);
            mma_gemm<128, 256, 2><<<grid1, 256, DSMEM>>>(
                t2, agg, eps, l, sc2,
                wt1h + wo, wt1l + wo, b1 + l * 256, t1, st1);
        }
        finalize_bn<<<1, 256>>>(st1, g1 + l * 256, bt1 + l * 256, sc1, 256);

        dim3 grid2(gemm_blocks, 1);
        mma_gemm<256, 128, 1><<<grid2, 256, DSMEM>>>(
            t1, (const float*)nullptr, (const float*)nullptr, 0, sc1,
            wt2h + wo, wt2l + wo, b2 + l * 128, t2, st2);
        finalize_bn<<<1, 128>>>(st2, go + l * 128, bto + l * 128, sc2, 128);
    }
    apply_bn<<<elem_blocks, 256>>>(t2, sc2, out);
}